// round 12
// baseline (speedup 1.0000x reference)
#include <cuda_runtime.h>

// EMA scan: SINGLE LAUNCH, role-split grid.
//   out[l,d,e] = a_e*x[l,d] + (1-a_e)*out[l-1,d,e],  out[-1,d,e] = x[0,d]
//
// CHUNK=32, oS_max = 0.9586^32 = 0.258; look-back J=8 -> trunc 2e-5 << 1e-3.
//
// Grid = 2048 blocks. bids 0..1023: aggr role (round-4 body) -> publish B[k,g]
// + monotonic flag. bids 1024..2047: scan role (round-4 body) -> poll the 8
// predecessor flags, Horner carry, scan chunk, streaming stores.
//
// Safety: CTA dispatch is bid-ordered, so every aggr block is dispatched
// before any scan block; aggr blocks never wait -> they retire -> scan blocks'
// dependencies always complete. Epochs: aggr thread0 publishes flag=old+1
// (single writer, runs are stream-serialized); each scan block keeps its own
// run counter and waits for flag >= run. No reset kernel needed.

#define LSEQ   8192
#define DFEAT  512
#define EMAS   8
#define CHUNK  32
#define NCHUNK (LSEQ / CHUNK)    // 256
#define DPB    128               // d's per block
#define NDG    (DFEAT / DPB)     // 4
#define NBLK   (NCHUNK * NDG)    // 1024 per role
#define TPB    (DPB * 2)         // 256 threads: 2 per d (4 states each)
#define LOOKB  8
#define NST    4                 // states per thread

__device__ float g_B[NCHUNK * DFEAT * EMAS];   // 4 MB scratch
__device__ int   g_flag[NBLK];                 // aggr publish counters (zero-init)
__device__ int   g_run[NBLK];                  // scan-side run counters (zero-init)

__device__ __forceinline__ void load_coeffs4(const float* __restrict__ log_decay,
                                             int e0, float* a, float* o)
{
    #pragma unroll
    for (int e = 0; e < NST; ++e) {
        float la = __ldg(log_decay + e0 + e);
        a[e] = 1.0f / (1.0f + expf(-la));
        o[e] = 1.0f - a[e];
    }
}

__global__ __launch_bounds__(TPB, 6)
void ema_combined(const float* __restrict__ x,
                  const float* __restrict__ log_decay,
                  float* __restrict__ out)
{
    const int bid = blockIdx.x;
    const int t   = threadIdx.x;
    const int dl  = t >> 1;             // 0..127
    const int e0  = (t & 1) * NST;      // 0 or 4

    if (bid < NBLK) {
        // ================= AGGR role =================
        const int k = bid / NDG;
        const int g = bid % NDG;
        const int d = g * DPB + dl;

        float a[NST], o[NST];
        load_coeffs4(log_decay, e0, a, o);

        float B[NST];
        #pragma unroll
        for (int e = 0; e < NST; ++e) B[e] = 0.0f;

        const float* xp = x + (size_t)k * CHUNK * DFEAT + d;
        #pragma unroll
        for (int ii = 0; ii < CHUNK; ii += 8) {
            float xv[8];
            #pragma unroll
            for (int j = 0; j < 8; ++j)           // front-batched, MLP=8
                xv[j] = xp[(size_t)(ii + j) * DFEAT];
            #pragma unroll
            for (int j = 0; j < 8; ++j)
                #pragma unroll
                for (int e = 0; e < NST; ++e)
                    B[e] = fmaf(o[e], B[e], a[e] * xv[j]);
        }

        *reinterpret_cast<float4*>(g_B + ((size_t)k * DFEAT + d) * EMAS + e0) =
            make_float4(B[0], B[1], B[2], B[3]);
        __threadfence();
        __syncthreads();                          // all B of this block visible
        if (t == 0) {
            // single writer per run; runs are stream-serialized
            ((volatile int*)g_flag)[bid] = g_flag[bid] + 1;
        }
    } else {
        // ================= SCAN role =================
        const int b2 = bid - NBLK;
        const int k  = b2 / NDG;
        const int g  = b2 % NDG;
        const int d  = g * DPB + dl;

        __shared__ int s_target;
        if (t == 0) {
            int r = g_run[b2] + 1;                // this run's index (1-based)
            g_run[b2] = r;
            s_target = r;
        }

        // carry-independent prep while s_target settles
        float a[NST], o[NST];
        load_coeffs4(log_decay, e0, a, o);

        float oS[NST];
        #pragma unroll
        for (int e = 0; e < NST; ++e) {
            float tmp = o[e];
            #pragma unroll
            for (int s = 0; s < 5; ++s) tmp *= tmp;   // o^32
            oS[e] = tmp;
        }
        const float x0 = (k <= LOOKB) ? __ldg(x + d) : 0.0f;

        __syncthreads();
        const int target = s_target;

        // wait for the min(k,LOOKB) predecessor aggr blocks (same d-group)
        const int m = (k < LOOKB) ? k : LOOKB;
        if (t < m) {
            while (((volatile int*)g_flag)[(k - 1 - t) * NDG + g] < target)
                __nanosleep(32);
        }
        __syncthreads();
        __threadfence();                          // acquire

        // carry: Horner oldest -> newest (exact x0 seed when k <= LOOKB)
        float c[NST];
        #pragma unroll
        for (int e = 0; e < NST; ++e) c[e] = (k <= LOOKB) ? x0 : 0.0f;

        const float* bb = g_B + (size_t)d * EMAS + e0;
        const size_t CSTRIDE = (size_t)DFEAT * EMAS;
        for (int j = m; j >= 1; --j) {
            const float4 bv = *reinterpret_cast<const float4*>(
                bb + (size_t)(k - j) * CSTRIDE);
            c[0] = fmaf(oS[0], c[0], bv.x);
            c[1] = fmaf(oS[1], c[1], bv.y);
            c[2] = fmaf(oS[2], c[2], bv.z);
            c[3] = fmaf(oS[3], c[3], bv.w);
        }

        // scan this chunk, streaming stores
        const float* xp = x + (size_t)k * CHUNK * DFEAT + d;
        float* op = out + ((size_t)k * CHUNK * DFEAT + d) * EMAS + e0;

        #pragma unroll
        for (int ii = 0; ii < CHUNK; ii += 8) {
            float xv[8];
            #pragma unroll
            for (int j = 0; j < 8; ++j)
                xv[j] = xp[(size_t)(ii + j) * DFEAT];
            #pragma unroll
            for (int j = 0; j < 8; ++j) {
                #pragma unroll
                for (int e = 0; e < NST; ++e)
                    c[e] = fmaf(o[e], c[e], a[e] * xv[j]);
                __stcs(reinterpret_cast<float4*>(
                           op + (size_t)(ii + j) * (DFEAT * EMAS)),
                       make_float4(c[0], c[1], c[2], c[3]));
            }
        }
    }
}

extern "C" void kernel_launch(void* const* d_in, const int* in_sizes, int n_in,
                              void* d_out, int out_size)
{
    const float* x  = (const float*)d_in[0];
    const float* ld = (const float*)d_in[1];
    if (n_in >= 2 && in_sizes[0] == EMAS && in_sizes[1] == LSEQ * DFEAT) {
        x  = (const float*)d_in[1];
        ld = (const float*)d_in[0];
    }
    float* out = (float*)d_out;

    ema_combined<<<2 * NBLK, TPB>>>(x, ld, out);   // 2048 blocks, one launch
}